// round 13
// baseline (speedup 1.0000x reference)
#include <cuda_runtime.h>
#include <cuda_fp16.h>
#include <math.h>

// Problem constants
#define BATCH    64
#define IN_CAPS  2048
#define IN_DIM   16
#define NUM_CAPS 32
#define OUT_DIM  16
#define JD       512            // NUM_CAPS * OUT_DIM
#define NCH      64             // chunks of 32 i (shared by producer + iters)
#define IC       (IN_CAPS/NCH)  // 32 i per chunk

// Scratch (device globals; allocation-free per harness rules)
__device__ __align__(16) __half g_uhat[(size_t)BATCH * IN_CAPS * JD];  // 128 MB, [b][i][j*16+d]
__device__ float g_spart[(size_t)BATCH * NCH * JD];  // 8 MB, d-major [b][c][d*32+j]
__device__ float g_out0[(size_t)BATCH * JD];         // d-major [b][d*32+j]
__device__ float g_out1[(size_t)BATCH * JD];

// ---- packed f32x2 helpers (sm_103a) ---------------------------------------
static __device__ __forceinline__ unsigned long long pack2(float lo, float hi) {
    unsigned long long r;
    asm("mov.b64 %0, {%1, %2};" : "=l"(r) : "f"(lo), "f"(hi));
    return r;
}
#define FMA2(d, a, b, c) asm("fma.rn.f32x2 %0, %1, %2, %3;" : "=l"(d) : "l"(a), "l"(b), "l"(c))
#define MUL2(d, a, b)    asm("mul.rn.f32x2 %0, %1, %2;"     : "=l"(d) : "l"(a), "l"(b))
#define ADD2(d, a, b)    asm("add.rn.f32x2 %0, %1, %2;"     : "=l"(d) : "l"(a), "l"(b))
#define UNPK2(lo, hi, v) asm("mov.b64 {%0, %1}, %2;" : "=f"(lo), "=f"(hi) : "l"(v))

// ---------------------------------------------------------------------------
// K1 fused: u_hat (fp16) + iter-0 partials, with NO per-i barriers.
// Grid (NCH=64 ic, 4 bq, 2 jh) = 512 blocks, 256 threads (thread = jd within
// half). All x for the block (16 b x 32 i) staged ONCE as (b0,b1) f32x2
// pairs; inner loop: W row -> regs (4 coalesced LDG.128), 8 b-pairs x
// 16 FMA2, s0 partial accumulated in 8 f32x2 regs, 2 STG.16 per pair
// (warp-contiguous 64B). s0 written once at the end, no atomics.
// ---------------------------------------------------------------------------
__global__ __launch_bounds__(256) void uhat_s0_kernel(
    const float* __restrict__ x, const float* __restrict__ W)
{
    const int ic  = blockIdx.x;
    const int bq  = blockIdx.y;
    const int jh  = blockIdx.z;
    const int t   = threadIdx.x;        // 0..255
    const int i0  = ic * IC;
    const int b0q = bq * 16;
    const int jd  = jh * 256 + t;

    // [bp][i][k] packed (b0,b1); pad 18 keeps 16B alignment, kills store conflicts
    __shared__ unsigned long long xs[8][IC][18];   // 36 KB

    {   // stage all x: thread -> (b-pair bp, i=sub); coalesced float4 loads
        const int bp  = t >> 5, sub = t & 31;
        const int b_0 = b0q + 2 * bp;
        const float4* p0 = (const float4*)(x + ((size_t)b_0       * IN_CAPS + i0 + sub) * IN_DIM);
        const float4* p1 = (const float4*)(x + ((size_t)(b_0 + 1) * IN_CAPS + i0 + sub) * IN_DIM);
        float4 u0 = p0[0], u1 = p0[1], u2 = p0[2], u3 = p0[3];
        float4 v0 = p1[0], v1 = p1[1], v2 = p1[2], v3 = p1[3];
        unsigned long long* dst = xs[bp][sub];
        dst[0]  = pack2(u0.x, v0.x); dst[1]  = pack2(u0.y, v0.y);
        dst[2]  = pack2(u0.z, v0.z); dst[3]  = pack2(u0.w, v0.w);
        dst[4]  = pack2(u1.x, v1.x); dst[5]  = pack2(u1.y, v1.y);
        dst[6]  = pack2(u1.z, v1.z); dst[7]  = pack2(u1.w, v1.w);
        dst[8]  = pack2(u2.x, v2.x); dst[9]  = pack2(u2.y, v2.y);
        dst[10] = pack2(u2.z, v2.z); dst[11] = pack2(u2.w, v2.w);
        dst[12] = pack2(u3.x, v3.x); dst[13] = pack2(u3.y, v3.y);
        dst[14] = pack2(u3.z, v3.z); dst[15] = pack2(u3.w, v3.w);
    }
    __syncthreads();    // the ONLY barrier

    unsigned long long acc_s[8];
    #pragma unroll
    for (int bp = 0; bp < 8; bp++) acc_s[bp] = 0ull;

    for (int ii = 0; ii < IC; ii++) {
        const int i = i0 + ii;

        const float4* Wr = (const float4*)(W + ((size_t)i * JD + jd) * IN_DIM);
        float4 w0 = Wr[0], w1 = Wr[1], w2 = Wr[2], w3 = Wr[3];
        unsigned long long wp[16];
        wp[0]  = pack2(w0.x, w0.x); wp[1]  = pack2(w0.y, w0.y);
        wp[2]  = pack2(w0.z, w0.z); wp[3]  = pack2(w0.w, w0.w);
        wp[4]  = pack2(w1.x, w1.x); wp[5]  = pack2(w1.y, w1.y);
        wp[6]  = pack2(w1.z, w1.z); wp[7]  = pack2(w1.w, w1.w);
        wp[8]  = pack2(w2.x, w2.x); wp[9]  = pack2(w2.y, w2.y);
        wp[10] = pack2(w2.z, w2.z); wp[11] = pack2(w2.w, w2.w);
        wp[12] = pack2(w3.x, w3.x); wp[13] = pack2(w3.y, w3.y);
        wp[14] = pack2(w3.z, w3.z); wp[15] = pack2(w3.w, w3.w);

        __half* uout = g_uhat + (size_t)i * JD + jd;
        #pragma unroll
        for (int bp = 0; bp < 8; bp++) {
            const ulonglong2* ap = (const ulonglong2*)xs[bp][ii];  // broadcast
            ulonglong2 a0 = ap[0], a1 = ap[1], a2 = ap[2], a3 = ap[3];
            ulonglong2 a4 = ap[4], a5 = ap[5], a6 = ap[6], a7 = ap[7];
            unsigned long long u;
            MUL2(u, wp[0],  a0.x);
            FMA2(u, wp[1],  a0.y, u);
            FMA2(u, wp[2],  a1.x, u);
            FMA2(u, wp[3],  a1.y, u);
            FMA2(u, wp[4],  a2.x, u);
            FMA2(u, wp[5],  a2.y, u);
            FMA2(u, wp[6],  a3.x, u);
            FMA2(u, wp[7],  a3.y, u);
            FMA2(u, wp[8],  a4.x, u);
            FMA2(u, wp[9],  a4.y, u);
            FMA2(u, wp[10], a5.x, u);
            FMA2(u, wp[11], a5.y, u);
            FMA2(u, wp[12], a6.x, u);
            FMA2(u, wp[13], a6.y, u);
            FMA2(u, wp[14], a7.x, u);
            FMA2(u, wp[15], a7.y, u);
            ADD2(acc_s[bp], acc_s[bp], u);
            float lo, hi;
            UNPK2(lo, hi, u);
            const int b = b0q + 2 * bp;
            uout[(size_t)b       * IN_CAPS * JD] = __float2half_rn(lo);
            uout[(size_t)(b + 1) * IN_CAPS * JD] = __float2half_rn(hi);
        }
    }

    // iter-0 partials (d-major pos = d*32 + j), disjoint per block -> no atomics
    const int pos = (jd & 15) * 32 + (jd >> 4);
    #pragma unroll
    for (int bp = 0; bp < 8; bp++) {
        const int b = b0q + 2 * bp;
        float lo, hi;
        UNPK2(lo, hi, acc_s[bp]);
        g_spart[((size_t)b       * NCH + ic) * JD + pos] = lo * (1.0f / NUM_CAPS);
        g_spart[((size_t)(b + 1) * NCH + ic) * JD + pos] = hi * (1.0f / NUM_CAPS);
    }
}

// ---------------------------------------------------------------------------
// Fused routing iteration (iters 1/2; proven pipelined config) + L2 ping-pong.
// Re-tiled to NCH=64 chunks of IC=32 i (grid 4096 blocks). Lane = j;
// agreement dot in half2; softmax without max subtraction (exact).
// iter1 logits = <u,out0>; iter2 logits = <u,out0+out1>.
// ---------------------------------------------------------------------------
__global__ __launch_bounds__(256, 3) void iter_kernel(int iter, int rev)
{
    const int b    = rev ? (BATCH - 1 - blockIdx.y) : blockIdx.y;
    const int ic   = rev ? (NCH - 1 - blockIdx.x)   : blockIdx.x;
    const int t    = threadIdx.x;
    const int w    = t >> 5;
    const int lane = t & 31;            // = j
    const int i0   = ic * IC;

    __half2 vout2[8];
    #pragma unroll
    for (int d2 = 0; d2 < 8; d2++) {
        float f0 = g_out0[(size_t)b * JD + (2 * d2)     * 32 + lane];
        float f1 = g_out0[(size_t)b * JD + (2 * d2 + 1) * 32 + lane];
        if (iter == 2) {
            f0 += g_out1[(size_t)b * JD + (2 * d2)     * 32 + lane];
            f1 += g_out1[(size_t)b * JD + (2 * d2 + 1) * 32 + lane];
        }
        vout2[d2] = __floats2half2_rn(f0, f1);
    }

    float acc[16];
    #pragma unroll
    for (int d = 0; d < 16; d++) acc[d] = 0.f;

    const __half* uhbase = g_uhat + ((size_t)b * IN_CAPS + i0) * JD + lane * 16;

    // prologue: loads for step 0
    uint4 ra0, ra1, rb0, rb1;
    {
        const uint4* pA = (const uint4*)(uhbase + (size_t)w * JD);
        const uint4* pB = (const uint4*)(uhbase + (size_t)(w + 8) * JD);
        ra0 = pA[0]; ra1 = pA[1];
        rb0 = pB[0]; rb1 = pB[1];
    }

    #pragma unroll
    for (int step = 0; step < 2; step++) {
        uint4 na0, na1, nb0, nb1;
        if (step < 1) {     // prefetch step+1 before consuming current
            const int iiA = w + 16;
            const uint4* pA = (const uint4*)(uhbase + (size_t)iiA * JD);
            const uint4* pB = (const uint4*)(uhbase + (size_t)(iiA + 8) * JD);
            na0 = pA[0]; na1 = pA[1];
            nb0 = pB[0]; nb1 = pB[1];
        }

        // Agreement dots for both i's (independent chains, ILP)
        __half2 hA = __hmul2(((const __half2*)&ra0)[0], vout2[0]);
        __half2 hB = __hmul2(((const __half2*)&rb0)[0], vout2[0]);
        #pragma unroll
        for (int d2 = 1; d2 < 4; d2++) {
            hA = __hfma2(((const __half2*)&ra0)[d2], vout2[d2], hA);
            hB = __hfma2(((const __half2*)&rb0)[d2], vout2[d2], hB);
        }
        #pragma unroll
        for (int d2 = 0; d2 < 4; d2++) {
            hA = __hfma2(((const __half2*)&ra1)[d2], vout2[4 + d2], hA);
            hB = __hfma2(((const __half2*)&rb1)[d2], vout2[4 + d2], hB);
        }
        float eA = __expf(__low2float(hA) + __high2float(hA));
        float eB = __expf(__low2float(hB) + __high2float(hB));

        float sA = eA, sB = eB;   // interleaved butterflies (no max pass)
        #pragma unroll
        for (int o = 16; o; o >>= 1) {
            sA += __shfl_xor_sync(0xffffffffu, sA, o);
            sB += __shfl_xor_sync(0xffffffffu, sB, o);
        }
        float cA = eA / sA;
        float cB = eB / sB;

        #pragma unroll
        for (int d2 = 0; d2 < 4; d2++) {
            float2 f = __half22float2(((const __half2*)&ra0)[d2]);
            acc[2 * d2]     = fmaf(cA, f.x, acc[2 * d2]);
            acc[2 * d2 + 1] = fmaf(cA, f.y, acc[2 * d2 + 1]);
            float2 g = __half22float2(((const __half2*)&ra1)[d2]);
            acc[8 + 2 * d2]     = fmaf(cA, g.x, acc[8 + 2 * d2]);
            acc[8 + 2 * d2 + 1] = fmaf(cA, g.y, acc[8 + 2 * d2 + 1]);
        }
        #pragma unroll
        for (int d2 = 0; d2 < 4; d2++) {
            float2 f = __half22float2(((const __half2*)&rb0)[d2]);
            acc[2 * d2]     = fmaf(cB, f.x, acc[2 * d2]);
            acc[2 * d2 + 1] = fmaf(cB, f.y, acc[2 * d2 + 1]);
            float2 g = __half22float2(((const __half2*)&rb1)[d2]);
            acc[8 + 2 * d2]     = fmaf(cB, g.x, acc[8 + 2 * d2]);
            acc[8 + 2 * d2 + 1] = fmaf(cB, g.y, acc[8 + 2 * d2 + 1]);
        }

        if (step < 1) {
            ra0 = na0; ra1 = na1;
            rb0 = nb0; rb1 = nb1;
        }
    }

    // Cross-warp reduce (d-major in smem: conflict-free)
    __shared__ float red[8][JD];
    #pragma unroll
    for (int d = 0; d < 16; d++) red[w][d * 32 + lane] = acc[d];
    __syncthreads();

    float s1 = 0.f, s2 = 0.f;
    #pragma unroll
    for (int ww = 0; ww < 8; ww++) {
        s1 += red[ww][t];
        s2 += red[ww][t + 256];
    }
    float* sp = g_spart + ((size_t)b * NCH + ic) * JD;
    sp[t]       = s1;
    sp[t + 256] = s2;
}

// ---------------------------------------------------------------------------
// Reduce partials over NCH chunks + squash. d-major positions: t = d*32 + j.
// which: 0 -> g_out0, 1 -> g_out1, 2 -> dout (permuted to [b][j][d]).
// ---------------------------------------------------------------------------
__global__ __launch_bounds__(512) void squash_kernel(int which, float* __restrict__ dout)
{
    const int b = blockIdx.x;
    const int t = threadIdx.x;

    const float* sp = g_spart + (size_t)b * NCH * JD + t;
    float s = 0.f;
    #pragma unroll
    for (int p = 0; p < NCH; p++) s += sp[(size_t)p * JD];

    __shared__ float s2s[NUM_CAPS];
    if (t < NUM_CAPS) s2s[t] = 0.f;
    __syncthreads();
    atomicAdd(&s2s[t & 31], s * s);
    __syncthreads();

    float s2 = s2s[t & 31];
    float scale = s2 / ((1.0f + s2) * sqrtf(s2 + 1e-7f));
    float v = s * scale;

    if (which == 2)      dout[(size_t)b * JD + (t & 31) * 16 + (t >> 5)] = v;
    else if (which == 0) g_out0[(size_t)b * JD + t] = v;
    else                 g_out1[(size_t)b * JD + t] = v;
}

// ---------------------------------------------------------------------------
extern "C" void kernel_launch(void* const* d_in, const int* in_sizes, int n_in,
                              void* d_out, int out_size)
{
    const float* x = (const float*)d_in[0];
    const float* W = (const float*)d_in[1];
    if (in_sizes[0] == (int)((size_t)IN_CAPS * NUM_CAPS * IN_DIM * OUT_DIM)) {
        const float* tmp = x; x = W; W = tmp;
    }
    float* out = (float*)d_out;

    dim3 ug(NCH, 4, 2);
    dim3 ig(NCH, BATCH);

    uhat_s0_kernel<<<ug, 256>>>(x, W);       // u_hat + iter-0 partials fused
    squash_kernel<<<BATCH, 512>>>(0, out);   // -> g_out0

    iter_kernel<<<ig, 256>>>(1, 1);          // reverse (ping-pong vs producer)
    squash_kernel<<<BATCH, 512>>>(1, out);   // -> g_out1

    iter_kernel<<<ig, 256>>>(2, 0);          // forward
    squash_kernel<<<BATCH, 512>>>(2, out);   // -> dout
}

// round 14
// speedup vs baseline: 1.2505x; 1.2505x over previous
#include <cuda_runtime.h>
#include <cuda_fp16.h>
#include <math.h>

// Problem constants
#define BATCH    64
#define IN_CAPS  2048
#define IN_DIM   16
#define NUM_CAPS 32
#define OUT_DIM  16
#define JD       512            // NUM_CAPS * OUT_DIM
#define NIC      32             // i-chunks per batch in iter kernel
#define IC       (IN_CAPS/NIC)  // 64 i's per block

// Scratch (device globals; allocation-free per harness rules)
__device__ __align__(16) __half g_uhat[(size_t)BATCH * IN_CAPS * JD];  // 128 MB, [b][i][j*16+d]
__device__ float g_spart[(size_t)BATCH * NIC * JD];  // 4 MB, d-major [b][ic][d*32+j]
__device__ float g_out0[(size_t)BATCH * JD];         // d-major [b][d*32+j]
__device__ float g_out1[(size_t)BATCH * JD];

// ---- packed f32x2 helpers (sm_103a) ---------------------------------------
static __device__ __forceinline__ unsigned long long pack2(float lo, float hi) {
    unsigned long long r;
    asm("mov.b64 %0, {%1, %2};" : "=l"(r) : "f"(lo), "f"(hi));
    return r;
}
#define FMA2(d, a, b, c) asm("fma.rn.f32x2 %0, %1, %2, %3;" : "=l"(d) : "l"(a), "l"(b), "l"(c))
#define MUL2(d, a, b)    asm("mul.rn.f32x2 %0, %1, %2;"     : "=l"(d) : "l"(a), "l"(b))

// ---------------------------------------------------------------------------
// K1 (proven R9/R12 config): u_hat[b,i,jd] = sum_k W[i,jd,k] * x[b,i,k].
// One block per i, 512 threads (t = jd). x staged in smem pre-packed as
// (b, b+1) f32x2 pairs; W row held in regs as (w,w) pairs. fma.rn.f32x2
// computes 2 batches per 16 packed FMAs. Coalesced W float4 reads.
// ---------------------------------------------------------------------------
__global__ __launch_bounds__(512) void uhat_kernel(
    const float* __restrict__ x, const float* __restrict__ W)
{
    const int i = blockIdx.x;
    const int t = threadIdx.x;          // 0..511

    __shared__ unsigned long long xp[32][16];   // 32 b-pairs x 16 k

    {
        int p = t >> 4, k = t & 15;     // 512 threads cover all 32*16
        float lo = x[((size_t)(2 * p)     * IN_CAPS + i) * IN_DIM + k];
        float hi = x[((size_t)(2 * p + 1) * IN_CAPS + i) * IN_DIM + k];
        xp[p][k] = pack2(lo, hi);
    }

    const float4* Wr = (const float4*)(W + ((size_t)i * JD + t) * IN_DIM);
    float4 w0 = Wr[0], w1 = Wr[1], w2 = Wr[2], w3 = Wr[3];
    unsigned long long wp[16];
    wp[0]  = pack2(w0.x, w0.x); wp[1]  = pack2(w0.y, w0.y);
    wp[2]  = pack2(w0.z, w0.z); wp[3]  = pack2(w0.w, w0.w);
    wp[4]  = pack2(w1.x, w1.x); wp[5]  = pack2(w1.y, w1.y);
    wp[6]  = pack2(w1.z, w1.z); wp[7]  = pack2(w1.w, w1.w);
    wp[8]  = pack2(w2.x, w2.x); wp[9]  = pack2(w2.y, w2.y);
    wp[10] = pack2(w2.z, w2.z); wp[11] = pack2(w2.w, w2.w);
    wp[12] = pack2(w3.x, w3.x); wp[13] = pack2(w3.y, w3.y);
    wp[14] = pack2(w3.z, w3.z); wp[15] = pack2(w3.w, w3.w);

    __syncthreads();

    __half* out = g_uhat + (size_t)i * JD + t;
    #pragma unroll 4
    for (int p = 0; p < 32; p++) {
        const ulonglong2* ap = (const ulonglong2*)xp[p];
        ulonglong2 a0 = ap[0], a1 = ap[1], a2 = ap[2], a3 = ap[3];
        ulonglong2 a4 = ap[4], a5 = ap[5], a6 = ap[6], a7 = ap[7];
        unsigned long long acc;
        MUL2(acc, wp[0],  a0.x);
        FMA2(acc, wp[1],  a0.y, acc);
        FMA2(acc, wp[2],  a1.x, acc);
        FMA2(acc, wp[3],  a1.y, acc);
        FMA2(acc, wp[4],  a2.x, acc);
        FMA2(acc, wp[5],  a2.y, acc);
        FMA2(acc, wp[6],  a3.x, acc);
        FMA2(acc, wp[7],  a3.y, acc);
        FMA2(acc, wp[8],  a4.x, acc);
        FMA2(acc, wp[9],  a4.y, acc);
        FMA2(acc, wp[10], a5.x, acc);
        FMA2(acc, wp[11], a5.y, acc);
        FMA2(acc, wp[12], a6.x, acc);
        FMA2(acc, wp[13], a6.y, acc);
        FMA2(acc, wp[14], a7.x, acc);
        FMA2(acc, wp[15], a7.y, acc);
        float lo, hi;
        asm("mov.b64 {%0, %1}, %2;" : "=f"(lo), "=f"(hi) : "l"(acc));
        out[(size_t)(2 * p)     * IN_CAPS * JD] = __float2half_rn(lo);
        out[(size_t)(2 * p + 1) * IN_CAPS * JD] = __float2half_rn(hi);
    }
}

// ---------------------------------------------------------------------------
// Fused routing iteration (proven R12 config) + L2 ping-pong + pipelining:
// the next step's 4 LDG.128 are issued before processing the current step,
// doubling per-warp MLP (8 outstanding LDG.128) to cover DRAM latency.
// Lane = j; agreement dot in half2; softmax without max subtraction (exact).
// iter1 logits = <u,out0>; iter2 = <u,out0+out1>.
// ---------------------------------------------------------------------------
__global__ __launch_bounds__(256, 3) void iter_kernel(int iter, int rev)
{
    const int b    = rev ? (BATCH - 1 - blockIdx.y) : blockIdx.y;
    const int ic   = rev ? (NIC - 1 - blockIdx.x)   : blockIdx.x;
    const int t    = threadIdx.x;
    const int w    = t >> 5;
    const int lane = t & 31;            // = j
    const int i0   = ic * IC;

    __half2 vout2[8];
    if (iter > 0) {
        #pragma unroll
        for (int d2 = 0; d2 < 8; d2++) {
            float f0 = g_out0[(size_t)b * JD + (2 * d2)     * 32 + lane];
            float f1 = g_out0[(size_t)b * JD + (2 * d2 + 1) * 32 + lane];
            if (iter == 2) {
                f0 += g_out1[(size_t)b * JD + (2 * d2)     * 32 + lane];
                f1 += g_out1[(size_t)b * JD + (2 * d2 + 1) * 32 + lane];
            }
            vout2[d2] = __floats2half2_rn(f0, f1);
        }
    }

    float acc[16];
    #pragma unroll
    for (int d = 0; d < 16; d++) acc[d] = 0.f;

    const __half* uhbase = g_uhat + ((size_t)b * IN_CAPS + i0) * JD + lane * 16;

    // prologue: loads for step 0
    uint4 ra0, ra1, rb0, rb1;
    {
        const uint4* pA = (const uint4*)(uhbase + (size_t)w * JD);
        const uint4* pB = (const uint4*)(uhbase + (size_t)(w + 8) * JD);
        ra0 = pA[0]; ra1 = pA[1];
        rb0 = pB[0]; rb1 = pB[1];
    }

    #pragma unroll
    for (int step = 0; step < 4; step++) {
        // prefetch step+1 BEFORE consuming the current data
        uint4 na0, na1, nb0, nb1;
        if (step < 3) {
            const int iiA = w + (step + 1) * 16;
            const uint4* pA = (const uint4*)(uhbase + (size_t)iiA * JD);
            const uint4* pB = (const uint4*)(uhbase + (size_t)(iiA + 8) * JD);
            na0 = pA[0]; na1 = pA[1];
            nb0 = pB[0]; nb1 = pB[1];
        }

        if (iter == 0) {
            #pragma unroll
            for (int half_sel = 0; half_sel < 2; half_sel++) {
                const __half2* v2 = (const __half2*)(half_sel ? &rb0 : &ra0);
                const __half2* v3 = (const __half2*)(half_sel ? &rb1 : &ra1);
                #pragma unroll
                for (int d2 = 0; d2 < 4; d2++) {
                    float2 f = __half22float2(v2[d2]);
                    acc[2 * d2]     += f.x;
                    acc[2 * d2 + 1] += f.y;
                    float2 g = __half22float2(v3[d2]);
                    acc[8 + 2 * d2]     += g.x;
                    acc[8 + 2 * d2 + 1] += g.y;
                }
            }
        } else {
            // Agreement dots for both i's (independent chains, ILP)
            __half2 hA = __hmul2(((const __half2*)&ra0)[0], vout2[0]);
            __half2 hB = __hmul2(((const __half2*)&rb0)[0], vout2[0]);
            #pragma unroll
            for (int d2 = 1; d2 < 4; d2++) {
                hA = __hfma2(((const __half2*)&ra0)[d2], vout2[d2], hA);
                hB = __hfma2(((const __half2*)&rb0)[d2], vout2[d2], hB);
            }
            #pragma unroll
            for (int d2 = 0; d2 < 4; d2++) {
                hA = __hfma2(((const __half2*)&ra1)[d2], vout2[4 + d2], hA);
                hB = __hfma2(((const __half2*)&rb1)[d2], vout2[4 + d2], hB);
            }
            float eA = __expf(__low2float(hA) + __high2float(hA));
            float eB = __expf(__low2float(hB) + __high2float(hB));

            float sA = eA, sB = eB;   // interleaved butterflies (no max pass)
            #pragma unroll
            for (int o = 16; o; o >>= 1) {
                sA += __shfl_xor_sync(0xffffffffu, sA, o);
                sB += __shfl_xor_sync(0xffffffffu, sB, o);
            }
            float cA = eA / sA;
            float cB = eB / sB;

            #pragma unroll
            for (int d2 = 0; d2 < 4; d2++) {
                float2 f = __half22float2(((const __half2*)&ra0)[d2]);
                acc[2 * d2]     = fmaf(cA, f.x, acc[2 * d2]);
                acc[2 * d2 + 1] = fmaf(cA, f.y, acc[2 * d2 + 1]);
                float2 g = __half22float2(((const __half2*)&ra1)[d2]);
                acc[8 + 2 * d2]     = fmaf(cA, g.x, acc[8 + 2 * d2]);
                acc[8 + 2 * d2 + 1] = fmaf(cA, g.y, acc[8 + 2 * d2 + 1]);
            }
            #pragma unroll
            for (int d2 = 0; d2 < 4; d2++) {
                float2 f = __half22float2(((const __half2*)&rb0)[d2]);
                acc[2 * d2]     = fmaf(cB, f.x, acc[2 * d2]);
                acc[2 * d2 + 1] = fmaf(cB, f.y, acc[2 * d2 + 1]);
                float2 g = __half22float2(((const __half2*)&rb1)[d2]);
                acc[8 + 2 * d2]     = fmaf(cB, g.x, acc[8 + 2 * d2]);
                acc[8 + 2 * d2 + 1] = fmaf(cB, g.y, acc[8 + 2 * d2 + 1]);
            }
        }

        if (step < 3) {
            ra0 = na0; ra1 = na1;
            rb0 = nb0; rb1 = nb1;
        }
    }

    if (iter == 0) {
        #pragma unroll
        for (int d = 0; d < 16; d++) acc[d] *= (1.0f / NUM_CAPS);
    }

    // Cross-warp reduce (d-major in smem: conflict-free)
    __shared__ float red[8][JD];
    #pragma unroll
    for (int d = 0; d < 16; d++) red[w][d * 32 + lane] = acc[d];
    __syncthreads();

    float s1 = 0.f, s2 = 0.f;
    #pragma unroll
    for (int ww = 0; ww < 8; ww++) {
        s1 += red[ww][t];
        s2 += red[ww][t + 256];
    }
    float* sp = g_spart + ((size_t)b * NIC + ic) * JD;
    sp[t]       = s1;
    sp[t + 256] = s2;
}

// ---------------------------------------------------------------------------
// Squash, split over j for 4x more blocks: grid (BATCH, 4), 128 threads.
// Block q owns j in [8q, 8q+8); thread t: jloc = t&7, d = t>>3.
// Sum over NIC chunks (same order as before), norm via smem atomicAdd over
// the block's 8 j-slots, then scale + store.
// which: 0 -> g_out0, 1 -> g_out1, 2 -> dout (permuted to [b][j][d]).
// ---------------------------------------------------------------------------
__global__ __launch_bounds__(128) void squash_kernel(int which, float* __restrict__ dout)
{
    const int b    = blockIdx.x;
    const int q    = blockIdx.y;
    const int t    = threadIdx.x;       // 0..127
    const int jloc = t & 7;
    const int d    = t >> 3;            // 0..15
    const int j    = q * 8 + jloc;
    const int pos  = d * 32 + j;        // d-major position

    const float* sp = g_spart + (size_t)b * NIC * JD + pos;
    float s = 0.f;
    #pragma unroll
    for (int p = 0; p < NIC; p++) s += sp[(size_t)p * JD];

    __shared__ float s2s[8];
    if (t < 8) s2s[t] = 0.f;
    __syncthreads();
    atomicAdd(&s2s[jloc], s * s);
    __syncthreads();

    float s2 = s2s[jloc];
    float scale = s2 / ((1.0f + s2) * sqrtf(s2 + 1e-7f));
    float v = s * scale;

    if (which == 2)      dout[(size_t)b * JD + j * 16 + d] = v;
    else if (which == 0) g_out0[(size_t)b * JD + pos] = v;
    else                 g_out1[(size_t)b * JD + pos] = v;
}

// ---------------------------------------------------------------------------
extern "C" void kernel_launch(void* const* d_in, const int* in_sizes, int n_in,
                              void* d_out, int out_size)
{
    const float* x = (const float*)d_in[0];
    const float* W = (const float*)d_in[1];
    if (in_sizes[0] == (int)((size_t)IN_CAPS * NUM_CAPS * IN_DIM * OUT_DIM)) {
        const float* tmp = x; x = W; W = tmp;
    }
    float* out = (float*)d_out;

    dim3 ig(NIC, BATCH);
    dim3 sg(BATCH, 4);

    // L2 ping-pong: uhat ascending-i; alternate direction each pass so every
    // pass starts on the L2-resident tail of the previous one.
    uhat_kernel<<<IN_CAPS, 512>>>(x, W);

    iter_kernel<<<ig, 256>>>(0, 1);          // reverse
    squash_kernel<<<sg, 128>>>(0, out);      // -> g_out0

    iter_kernel<<<ig, 256>>>(1, 0);          // forward
    squash_kernel<<<sg, 128>>>(1, out);      // -> g_out1

    iter_kernel<<<ig, 256>>>(2, 1);          // reverse
    squash_kernel<<<sg, 128>>>(2, out);      // -> dout
}